// round 3
// baseline (speedup 1.0000x reference)
#include <cuda_runtime.h>

#define SS   512
#define HH   64
#define OUTN 12
#define BT   16           // batch per CTA
#define CTAS 128
#define NTHR 256
#define HS   20           // padded h row stride (floats)
#define XCH  64           // x staging chunk (timesteps)

typedef unsigned long long ull;

__device__ __forceinline__ ull pk2(float x, float y) {
    ull r; asm("mov.b64 %0, {%1, %2};" : "=l"(r) : "f"(x), "f"(y)); return r;
}
__device__ __forceinline__ void upk2(ull v, float& x, float& y) {
    asm("mov.b64 {%0, %1}, %2;" : "=f"(x), "=f"(y) : "l"(v));
}
__device__ __forceinline__ void fma2(ull& d, ull a, ull b) {
    asm("fma.rn.f32x2 %0, %1, %2, %0;" : "+l"(d) : "l"(a), "l"(b));
}
__device__ __forceinline__ float tanhax(float x) {
    float r; asm("tanh.approx.f32 %0, %1;" : "=f"(r) : "f"(x)); return r;
}
__device__ __forceinline__ float sig_t(float x) {   // sigmoid via MUFU.TANH (1 MUFU)
    return fmaf(0.5f, tanhax(0.5f * x), 0.5f);
}
__device__ __forceinline__ float tanh_ex(float x) { // exact-ish tanh for cell state
    return __fdividef(2.f, 1.f + __expf(-2.f * x)) - 1.f;
}

// 64-step MAC for 2 gates x 4 batch-pairs.
// Wp: float2 per j (this thread's 2 gates for unit u), stride 128 float2 per j.
// hrow: h state, u-major rows of HS floats; loads are warp-uniform (broadcast).
__device__ __forceinline__ void mac64(ull a[2][4], const float2* __restrict__ Wp,
                                      const float* __restrict__ hrow, int pb0) {
#pragma unroll 8
    for (int j = 0; j < 64; j++) {
        float2 w = Wp[j * 128];
        ulonglong2 ha = *(const ulonglong2*)(hrow + j * HS + pb0);
        ulonglong2 hb = *(const ulonglong2*)(hrow + j * HS + pb0 + 4);
        ull w0 = pk2(w.x, w.x), w1 = pk2(w.y, w.y);
        fma2(a[0][0], w0, ha.x); fma2(a[0][1], w0, ha.y);
        fma2(a[0][2], w0, hb.x); fma2(a[0][3], w0, hb.y);
        fma2(a[1][0], w1, ha.x); fma2(a[1][1], w1, ha.y);
        fma2(a[1][2], w1, hb.x); fma2(a[1][3], w1, hb.y);
    }
}

// Write this thread's 2 gates for the 2 pairs it does NOT update (pair-swap with gh^1).
__device__ __forceinline__ void exch_write(ull a[2][4], ull* exch, int gh, int pg, int u) {
    int gho = gh ^ 1;
#pragma unroll
    for (int pp = 0; pp < 2; pp++) {
        exch[((((gh * 2 + 0) * 2 + pp) * 2 + pg) << 6) + u] = a[0][gho * 2 + pp];
        exch[((((gh * 2 + 1) * 2 + pp) * 2 + pg) << 6) + u] = a[1][gho * 2 + pp];
    }
}

// Full LSTM cell update for this thread's 2 pairs (4 scalars); reads partner gates
// from exch (must be called after the barrier). Stores h (4 floats) to hn_dst.
__device__ __forceinline__ void cell_half(ull a[2][4], const ull* exch, int gh, int pg,
                                          int u, float c[4], float* hn_dst) {
    int gho = gh ^ 1;
    float hv[4];
#pragma unroll
    for (int pp = 0; pp < 2; pp++) {
        ull own0 = a[0][gh * 2 + pp], own1 = a[1][gh * 2 + pp];
        ull oth0 = exch[((((gho * 2 + 0) * 2 + pp) * 2 + pg) << 6) + u];
        ull oth1 = exch[((((gho * 2 + 1) * 2 + pp) * 2 + pg) << 6) + u];
        ull iv = gh ? oth0 : own0;   // gate order: i, f, g, o
        ull fv = gh ? oth1 : own1;
        ull gv = gh ? own0 : oth0;
        ull ov = gh ? own1 : oth1;
        float i0, i1, f0, f1, g0, g1, o0, o1;
        upk2(iv, i0, i1); upk2(fv, f0, f1); upk2(gv, g0, g1); upk2(ov, o0, o1);
        int k = 2 * pp;
        c[k]     = fmaf(sig_t(f0), c[k],     sig_t(i0) * tanhax(g0));
        c[k + 1] = fmaf(sig_t(f1), c[k + 1], sig_t(i1) * tanhax(g1));
        hv[k]     = sig_t(o0) * tanh_ex(c[k]);
        hv[k + 1] = sig_t(o1) * tanh_ex(c[k + 1]);
    }
    *(float4*)hn_dst = make_float4(hv[0], hv[1], hv[2], hv[3]);
}

__global__ void __launch_bounds__(NTHR, 1) lstm2_kernel(
    const float* __restrict__ x,
    const float* __restrict__ w_ih0, const float* __restrict__ w_hh0,
    const float* __restrict__ b_ih0, const float* __restrict__ b_hh0,
    const float* __restrict__ w_ih1, const float* __restrict__ w_hh1,
    const float* __restrict__ b_ih1, const float* __restrict__ b_hh1,
    const float* __restrict__ fc_w, const float* __restrict__ fc_b,
    float* __restrict__ out)
{
    extern __shared__ float sm[];
    float2* W0f = (float2*)sm;          // [64 j][2 gh][64 u] float2 (gates 2gh,2gh+1)
    float2* W1f = W0f + 64 * 128;
    float2* W2f = W1f + 64 * 128;
    float* h0s = (float*)(W2f + 64 * 128);  // [2 buf][64 u][HS]
    float* h1s = h0s + 2 * 64 * HS;
    float* xs  = h1s + 2 * 64 * HS;         // [XCH][16]
    ull*  exch = (ull*)(xs + XCH * 16);     // [gh][kk][pp][pg][64 u]

    const int tid = threadIdx.x;
    const int u   = tid & 63;
    const int gh  = (tid >> 6) & 1;   // gate half: 0 -> {i,f}, 1 -> {g,o}
    const int pg  = tid >> 7;         // batch half
    const int pb0 = pg * 8;
    const int b0  = blockIdx.x * BT;

    // ---- stage weights: W[mat][j][gh][u] = (w[2gh][u][j], w[2gh+1][u][j]) ----
    for (int e = tid; e < 64 * 64; e += NTHR) {
        int j = e & 63, uu = e >> 6;   // lanes sweep j -> coalesced gmem reads
        W0f[j * 128 +      uu] = make_float2(w_hh0[uu * 64 + j],         w_hh0[(64 + uu) * 64 + j]);
        W0f[j * 128 + 64 + uu] = make_float2(w_hh0[(128 + uu) * 64 + j], w_hh0[(192 + uu) * 64 + j]);
        W1f[j * 128 +      uu] = make_float2(w_ih1[uu * 64 + j],         w_ih1[(64 + uu) * 64 + j]);
        W1f[j * 128 + 64 + uu] = make_float2(w_ih1[(128 + uu) * 64 + j], w_ih1[(192 + uu) * 64 + j]);
        W2f[j * 128 +      uu] = make_float2(w_hh0 == w_hh1 ? 0.f : w_hh1[uu * 64 + j], w_hh1[(64 + uu) * 64 + j]);
        W2f[j * 128 +      uu].x = w_hh1[uu * 64 + j];
        W2f[j * 128 + 64 + uu] = make_float2(w_hh1[(128 + uu) * 64 + j], w_hh1[(192 + uu) * 64 + j]);
    }
    for (int e = tid; e < 2 * 64 * HS; e += NTHR) { h0s[e] = 0.f; h1s[e] = 0.f; }

    // per-thread constants (own 2 gates only)
    ull bias0p[2], bias1p[2], wih0p[2];
#pragma unroll
    for (int k = 0; k < 2; k++) {
        int g = 2 * gh + k;
        float v0 = b_ih0[g * 64 + u] + b_hh0[g * 64 + u];
        float v1 = b_ih1[g * 64 + u] + b_hh1[g * 64 + u];
        float wi = w_ih0[g * 64 + u];   // INPUT_SIZE == 1
        bias0p[k] = pk2(v0, v0);
        bias1p[k] = pk2(v1, v1);
        wih0p[k]  = pk2(wi, wi);
    }

    float c0[4], c1[4];
#pragma unroll
    for (int i = 0; i < 4; i++) { c0[i] = 0.f; c1[i] = 0.f; }

    __syncthreads();

    int cur = 0;
    for (int t = 0; t < SS; t++) {
        if ((t & (XCH - 1)) == 0) {
            __syncthreads();
            for (int e = tid; e < BT * XCH; e += NTHR) {
                int tc = e & (XCH - 1), b = e >> 6;
                xs[tc * 16 + b] = x[(size_t)(b0 + b) * SS + t + tc];
            }
            __syncthreads();
        }

        const float* h0c = h0s + cur * 64 * HS;
        const float* h1c = h1s + cur * 64 * HS;
        float* h0n = h0s + (cur ^ 1) * 64 * HS;
        float* h1n = h1s + (cur ^ 1) * 64 * HS;

        ull a[2][4];

        // ================= layer 0 =================
        {
            int tloc = t & (XCH - 1);
            ulonglong2 xa = *(const ulonglong2*)(xs + tloc * 16 + pb0);
            ulonglong2 xb = *(const ulonglong2*)(xs + tloc * 16 + pb0 + 4);
#pragma unroll
            for (int k = 0; k < 2; k++) {
                a[k][0] = bias0p[k]; a[k][1] = bias0p[k];
                a[k][2] = bias0p[k]; a[k][3] = bias0p[k];
                fma2(a[k][0], wih0p[k], xa.x); fma2(a[k][1], wih0p[k], xa.y);
                fma2(a[k][2], wih0p[k], xb.x); fma2(a[k][3], wih0p[k], xb.y);
            }
            mac64(a, W0f + gh * 64 + u, h0c, pb0);
        }
        exch_write(a, exch, gh, pg, u);
        __syncthreads();
        cell_half(a, exch, gh, pg, u, c0, h0n + u * HS + pg * 8 + gh * 4);
        __syncthreads();

        // ================= layer 1 =================
#pragma unroll
        for (int k = 0; k < 2; k++) {
            a[k][0] = bias1p[k]; a[k][1] = bias1p[k];
            a[k][2] = bias1p[k]; a[k][3] = bias1p[k];
        }
        mac64(a, W1f + gh * 64 + u, h0n, pb0);
        mac64(a, W2f + gh * 64 + u, h1c, pb0);
        exch_write(a, exch, gh, pg, u);
        __syncthreads();
        cell_half(a, exch, gh, pg, u, c1, h1n + u * HS + pg * 8 + gh * 4);
        __syncthreads();

        cur ^= 1;
    }

    // ================= final projection =================
    const float* hf = h1s + cur * 64 * HS;
    for (int idx = tid; idx < BT * OUTN; idx += NTHR) {
        int b = idx / OUTN, o = idx - b * OUTN;
        float s = fc_b[o];
#pragma unroll 16
        for (int uu = 0; uu < 64; uu++)
            s += hf[uu * HS + b] * fc_w[o * 64 + uu];
        out[(size_t)(b0 + b) * OUTN + o] = s;
    }
}

extern "C" void kernel_launch(void* const* d_in, const int* in_sizes, int n_in,
                              void* d_out, int out_size) {
    (void)in_sizes; (void)n_in; (void)out_size;
    const float* x     = (const float*)d_in[0];
    const float* w_ih0 = (const float*)d_in[1];
    const float* w_hh0 = (const float*)d_in[2];
    const float* b_ih0 = (const float*)d_in[3];
    const float* b_hh0 = (const float*)d_in[4];
    const float* w_ih1 = (const float*)d_in[5];
    const float* w_hh1 = (const float*)d_in[6];
    const float* b_ih1 = (const float*)d_in[7];
    const float* b_hh1 = (const float*)d_in[8];
    const float* fc_w  = (const float*)d_in[9];
    const float* fc_b  = (const float*)d_in[10];

    size_t smem = (size_t)(3 * 64 * 128 * 2 + 4 * 64 * HS + XCH * 16) * sizeof(float)
                + (size_t)1024 * sizeof(ull);
    cudaFuncSetAttribute(lstm2_kernel, cudaFuncAttributeMaxDynamicSharedMemorySize, (int)smem);
    lstm2_kernel<<<CTAS, NTHR, smem>>>(x, w_ih0, w_hh0, b_ih0, b_hh0,
                                       w_ih1, w_hh1, b_ih1, b_hh1,
                                       fc_w, fc_b, (float*)d_out);
}